// round 13
// baseline (speedup 1.0000x reference)
#include <cuda_runtime.h>
#include <math.h>
#include <float.h>

// ---------------- problem constants (fixed by setup_inputs) ----------------
static constexpr int NCAM = 6;
static constexpr int CCH  = 64;
static constexpr int NCQ  = CCH / 4;           // 16 channel quads
static constexpr int HF   = 64;
static constexpr int WF   = 176;
static constexpr int SLICE = HF * WF;          // 11264
static constexpr int ZD   = 129;
static constexpr int XD   = 129;
static constexpr int NY   = 4;
static constexpr int NH   = 3;                 // NY-1
static constexpr int DD   = 128;               // ZD-1
static constexpr int WDIM = 128;               // XD-1
static constexpr int P    = DD * WDIM;         // 16384 = 2^14
static constexpr int NREC = NCAM * NH * P;     // 294912
static constexpr float EPS_F = 1e-6f;

// ---------------- device scratch (no dynamic allocation allowed) -----------
__device__ float  d_rowsum[NCAM * CCH * SLICE];      // row-prefixed features
__device__ float  d_integ4[NCAM * NCQ * SLICE * 4];  // integral, quad-interleaved
__device__ int4   g_xi[NREC];                        // 4 column indices
__device__ int4   g_yo[NREC];                        // 4 row offsets (y*WF)
__device__ float4 g_wa[NREC];                        // 4 signed column weights
__device__ float4 g_wb[NREC];                        // 4 signed row weights
__device__ float  g_sc[NREC];                        // 1/area (0 if degenerate)

// ---------------- kernel 1a: row prefix scan (one warp per image row) -------
// 24576 warps of independent work; shfl Kogge-Stone scan per 32-chunk with
// carry propagation. No smem, no __syncthreads, fully coalesced.
__global__ void __launch_bounds__(256) oft_rowscan(const float* __restrict__ feat) {
    const int warp = (blockIdx.x * blockDim.x + threadIdx.x) >> 5;
    const int lane = threadIdx.x & 31;
    if (warp >= NCAM * CCH * HF) return;
    const float* src = feat + (size_t)warp * WF;
    float* dst = d_rowsum + (size_t)warp * WF;

    float carry = 0.f;
    #pragma unroll
    for (int c = 0; c < 6; ++c) {              // 176 = 5*32 + 16
        const int x = c * 32 + lane;
        float v = (x < WF) ? src[x] : 0.f;
        #pragma unroll
        for (int o = 1; o < 32; o <<= 1) {
            const float n = __shfl_up_sync(0xffffffffu, v, o);
            if (lane >= o) v += n;
        }
        v += carry;
        if (x < WF) dst[x] = v;
        carry = __shfl_sync(0xffffffffu, v, 31);
    }
}

// ---------------- kernel 1b: column prefix + quad-interleaved store ---------
// One thread per (cam, ch, x) column = 67584 threads; 64 y-steps each with
// coalesced loads (consecutive x per lane). Writes the final
// [cam][cq][pix][4ch] layout (16B-stride scalar stores, ~2us class).
__global__ void __launch_bounds__(256) oft_colscan() {
    const int col = blockIdx.x * blockDim.x + threadIdx.x;
    if (col >= NCAM * CCH * WF) return;
    const int x  = col % WF;
    const int s  = col / WF;                   // cam*CCH + ch
    const int ch = s % CCH;
    const int cam = s / CCH;

    const float* src = d_rowsum + (size_t)s * SLICE + x;
    float* dst = d_integ4 + ((size_t)(cam * NCQ + (ch >> 2)) * SLICE) * 4 + (ch & 3);

    float acc = 0.f;
    #pragma unroll 8
    for (int y = 0; y < HF; ++y) {
        acc += src[(size_t)y * WF];
        dst[(size_t)(y * WF + x) * 4] = acc;
    }
}

// ---------------- kernel 2: FUSED project + geometry ------------------------
__device__ __forceinline__ void map_axis(float c, int extent,
                                         int& i0, int& i1, float& w) {
    const float lim = (float)(extent - 1);
    const float v = fminf(fmaxf((c + 1.f) * 0.5f * lim, 0.f), lim);
    const float f = floorf(v);
    i0 = (int)f;
    w = v - f;
    i1 = min(i0 + 1, extent - 1);
}

__global__ void __launch_bounds__(128) oft_geometry(
        const float* __restrict__ ks,
        const float* __restrict__ imu2cs,
        const float* __restrict__ prs,
        const float* __restrict__ ptr_,
        const float* __restrict__ und,
        const float* __restrict__ grid) {
    __shared__ float2 sp[2][2][XD];    // [ny][z][x]
    const int blk = blockIdx.x;        // (cam*NH + nh)*DD + d
    const int d   = blk % DD;
    const int nh  = (blk / DD) % NH;
    const int cam = blk / (DD * NH);

    const float* K = ks + cam * 9;
    const float* M = imu2cs + cam * 12;
    float cal[12];
    #pragma unroll
    for (int i = 0; i < 3; ++i)
        #pragma unroll
        for (int j = 0; j < 4; ++j)
            cal[i * 4 + j] = K[i * 3 + 0] * M[0 * 4 + j]
                           + K[i * 3 + 1] * M[1 * 4 + j]
                           + K[i * 3 + 2] * M[2 * 4 + j];
    const float fx = K[0], fy = K[4], cx = K[2], cy = K[5];
    const float* D = und + cam * 7;
    const float* PR = prs + cam * 9;
    const float* PT = ptr_ + cam * 3;

    for (int i = threadIdx.x; i < 2 * 2 * XD; i += blockDim.x) {
        const int x = i % XD;
        const int b = (i / XD) & 1;    // z offset
        const int a = i / (XD * 2);    // ny offset
        const float* g = grid + (size_t)((d + b) * XD + x) * 3;
        const float X = g[0];
        const float Y = g[1] + (2.0f - (float)(nh + a));  // ys = -arange(0,4)+2
        const float Z = g[2];

        float hx = cal[0] * X + cal[1] * Y + cal[2]  * Z + cal[3];
        float hy = cal[4] * X + cal[5] * Y + cal[6]  * Z + cal[7];
        float hz = cal[8] * X + cal[9] * Y + cal[10] * Z + cal[11];
        const bool pos = hz > 0.f;
        if (!pos) { hx = 0.f; hy = 0.f; }        // flag zeroes x,y behind cam
        const float px = hx / hz;
        const float py = hy / hz;

        const float xn = (px - cx) / fx;
        const float yn = (py - cy) / fy;
        float xd, yd;
        if (D[6] == 1.0f) {                      // fisheye
            const float r  = sqrtf(xn * xn + yn * yn);
            const float th = atanf(r);
            const float t2 = th * th, t4 = t2 * t2, t6 = t4 * t2, t8 = t4 * t4;
            const float rad = th * (1.f + D[0] * t2 + D[1] * t4 + D[2] * t6 + D[5] * t8) / r;
            xd = xn * rad * fx + cx;
            yd = yn * rad * fy + cy;
        } else {                                 // pinhole + tangential
            const float k1 = D[0], k2 = D[1], k3 = D[2], p1 = D[3], p2 = D[4];
            const float r2 = xn * xn + yn * yn;
            const float poly = 1.f + k1 * r2 + k2 * r2 * r2 + k3 * r2 * r2 * r2;
            const float xdd = xn * poly + (2.f * p1 * xn * yn + p2 * (r2 + 2.f * xn * xn));
            const float ydd = yn * poly + (p1 * (r2 + 2.f * yn * yn) + 2.f * p2 * xn * yn);
            xd = xdd * fx + cx;
            yd = ydd * fy + cy;
        }
        const float fl = pos ? 1.f : 0.f;
        xd *= fl; yd *= fl;

        const float qx = PR[0] * xd + PR[1] * yd + PT[0];
        const float qy = PR[3] * xd + PR[4] * yd + PT[1];
        sp[a][b][x] = make_float2(fminf(fmaxf(2.f * qx - 1.f, -1.f), 1.f),
                                  fminf(fmaxf(2.f * qy - 1.f, -1.f), 1.f));
    }
    __syncthreads();

    const int wd = threadIdx.x;
    float left = FLT_MAX, right = -FLT_MAX, top = FLT_MAX, bot = -FLT_MAX;
    #pragma unroll
    for (int a = 0; a < 2; ++a)
        #pragma unroll
        for (int b = 0; b < 2; ++b)
            #pragma unroll
            for (int c = 0; c < 2; ++c) {
                const float2 v = sp[a][b][wd + c];
                left  = fminf(left,  v.x);  right = fmaxf(right, v.x);
                top   = fminf(top,   v.y);  bot   = fmaxf(bot,   v.y);
            }

    const float area = (right - left) * (bot - top) * ((float)HF * (float)WF * 0.25f) + EPS_F;
    const float sc = (area > EPS_F) ? (1.f / area) : 0.f;

    int xl0, xl1, xr0, xr1, yt0, yt1, yb0, yb1;
    float wxl, wxr, wyt, wyb;
    map_axis(left,  WF, xl0, xl1, wxl);
    map_axis(right, WF, xr0, xr1, wxr);
    map_axis(top,   HF, yt0, yt1, wyt);
    map_axis(bot,   HF, yb0, yb1, wyb);

    const int idx = (cam * NH + nh) * P + d * WDIM + wd;
    // value = sum_j wb_j * sum_i wa_i * I[yo_j + xi_i]  (tl+br-tr-bl separable)
    g_xi[idx] = make_int4(xl0, xl1, xr0, xr1);
    g_wa[idx] = make_float4(1.f - wxl, wxl, -(1.f - wxr), -wxr);
    g_yo[idx] = make_int4(yt0 * WF, yt1 * WF, yb0 * WF, yb1 * WF);
    g_wb[idx] = make_float4(1.f - wyt, wyt, -(1.f - wyb), -wyb);
    g_sc[idx] = sc;
}

// ---------------- float4 helpers -------------------------------------------
__device__ __forceinline__ float4 f4_scale(float s, float4 a) {
    return make_float4(s * a.x, s * a.y, s * a.z, s * a.w);
}
__device__ __forceinline__ float4 f4_fma(float s, float4 a, float4 acc) {
    return make_float4(fmaf(s, a.x, acc.x), fmaf(s, a.y, acc.y),
                       fmaf(s, a.z, acc.z), fmaf(s, a.w, acc.w));
}

// ---------------- kernel 3: gather + max over cameras (dominant) ------------
// R8 configuration verbatim — best measured: 68.8us, occ 56.9, L1 78.2%.
__global__ void __launch_bounds__(256, 5) oft_sample(float* __restrict__ out) {
    const int t = blockIdx.x * blockDim.x + threadIdx.x;
    const int p  = t & (P - 1);
    const int nh = (t >> 14) % NH;
    const int cq = t / (P * NH);          // channel quad 0..15

    float4 m = make_float4(-INFINITY, -INFINITY, -INFINITY, -INFINITY);

    #pragma unroll
    for (int cam = 0; cam < NCAM; ++cam) {
        const int rec = (cam * NH + nh) * P + p;
        const float sc = __ldg(&g_sc[rec]);
        if (sc != 0.f) {
            const int4   xi = __ldg(&g_xi[rec]);
            const int4   yo = __ldg(&g_yo[rec]);
            const float4 wa = __ldg(&g_wa[rec]);
            const float4 wb = __ldg(&g_wb[rec]);
            const float4* base = reinterpret_cast<const float4*>(d_integ4)
                               + (size_t)(cam * NCQ + cq) * SLICE;

            float4 acc;
            {
                const float4* r = base + yo.x;
                float4 s = f4_scale(wa.x, __ldg(r + xi.x));
                s = f4_fma(wa.y, __ldg(r + xi.y), s);
                s = f4_fma(wa.z, __ldg(r + xi.z), s);
                s = f4_fma(wa.w, __ldg(r + xi.w), s);
                acc = f4_scale(wb.x, s);
            }
            {
                const float4* r = base + yo.y;
                float4 s = f4_scale(wa.x, __ldg(r + xi.x));
                s = f4_fma(wa.y, __ldg(r + xi.y), s);
                s = f4_fma(wa.z, __ldg(r + xi.z), s);
                s = f4_fma(wa.w, __ldg(r + xi.w), s);
                acc = f4_fma(wb.y, s, acc);
            }
            {
                const float4* r = base + yo.z;
                float4 s = f4_scale(wa.x, __ldg(r + xi.x));
                s = f4_fma(wa.y, __ldg(r + xi.y), s);
                s = f4_fma(wa.z, __ldg(r + xi.z), s);
                s = f4_fma(wa.w, __ldg(r + xi.w), s);
                acc = f4_fma(wb.z, s, acc);
            }
            {
                const float4* r = base + yo.w;
                float4 s = f4_scale(wa.x, __ldg(r + xi.x));
                s = f4_fma(wa.y, __ldg(r + xi.y), s);
                s = f4_fma(wa.z, __ldg(r + xi.z), s);
                s = f4_fma(wa.w, __ldg(r + xi.w), s);
                acc = f4_fma(wb.w, s, acc);
            }
            m.x = fmaxf(m.x, acc.x * sc);
            m.y = fmaxf(m.y, acc.y * sc);
            m.z = fmaxf(m.z, acc.z * sc);
            m.w = fmaxf(m.w, acc.w * sc);
        } else {
            m.x = fmaxf(m.x, 0.f);
            m.y = fmaxf(m.y, 0.f);
            m.z = fmaxf(m.z, 0.f);
            m.w = fmaxf(m.w, 0.f);
        }
    }

    float* o = out + (size_t)(cq * 4 * NH + nh) * P + p;
    o[0]                  = m.x;
    o[(size_t)NH * P]     = m.y;
    o[(size_t)2 * NH * P] = m.z;
    o[(size_t)3 * NH * P] = m.w;
}

// ---------------- launch --------------------------------------------------
extern "C" void kernel_launch(void* const* d_in, const int* in_sizes, int n_in,
                              void* d_out, int out_size) {
    const float* features  = (const float*)d_in[0];
    const float* ks        = (const float*)d_in[1];
    const float* imu2cs    = (const float*)d_in[2];
    const float* post_rots = (const float*)d_in[3];
    const float* post_tran = (const float*)d_in[4];
    const float* undists   = (const float*)d_in[5];
    const float* grid      = (const float*)d_in[6];
    float* out = (float*)d_out;

    const int nrows = NCAM * CCH * HF;         // 24576 rows, 1 warp each
    oft_rowscan<<<nrows / 8, 256>>>(features);

    const int ncols = NCAM * CCH * WF;         // 67584 columns, 1 thread each
    oft_colscan<<<(ncols + 255) / 256, 256>>>();

    oft_geometry<<<NCAM * NH * DD, 128>>>(ks, imu2cs, post_rots, post_tran,
                                          undists, grid);

    const int nsamp = NCQ * NH * P;            // 786432 threads
    oft_sample<<<(nsamp + 255) / 256, 256>>>(out);
}

// round 14
// speedup vs baseline: 1.1340x; 1.1340x over previous
#include <cuda_runtime.h>
#include <math.h>
#include <float.h>

// ---------------- problem constants (fixed by setup_inputs) ----------------
static constexpr int NCAM = 6;
static constexpr int CCH  = 64;
static constexpr int NCQ  = CCH / 4;           // 16 channel quads
static constexpr int HF   = 64;
static constexpr int WF   = 176;
static constexpr int SLICE = HF * WF;          // 11264
static constexpr int ZD   = 129;
static constexpr int XD   = 129;
static constexpr int NY   = 4;
static constexpr int NH   = 3;                 // NY-1
static constexpr int DD   = 128;               // ZD-1
static constexpr int WDIM = 128;               // XD-1
static constexpr int P    = DD * WDIM;         // 16384 = 2^14
static constexpr int NREC = NCAM * NH * P;     // 294912
static constexpr float EPS_F = 1e-6f;

// ---------------- device scratch (no dynamic allocation allowed) -----------
__device__ float  d_integ4[NCAM * NCQ * SLICE * 4];  // integral, quad-interleaved
__device__ int4   g_xi[NREC];                        // 4 column indices
__device__ int4   g_yo[NREC];                        // 4 row offsets (y*WF)
__device__ float4 g_wa[NREC];                        // 4 signed column weights
__device__ float4 g_wb[NREC];                        // 4 signed row weights
__device__ float  g_sc[NREC];                        // 1/area (0 if degenerate)

// ---------------- kernel 1: integral image, single pass, no staging ---------
// One block per (cam, ch) slice. Row phase: 8 warps x 8 rows via shfl
// Kogge-Stone scan straight from gmem (all 256 threads busy, no div/mod,
// no staging loop). Column phase: 176 threads, pipelined 64-step smem chain,
// storing directly into the quad-interleaved gmem layout.
__global__ void __launch_bounds__(256) oft_integral(const float* __restrict__ feat) {
    __shared__ float sh[HF][WF + 1];   // row-prefixed slice (+1: conflict-free cols)
    const int s = blockIdx.x;          // 0..NCAM*CCH-1
    const int cam = s / CCH;
    const int ch  = s % CCH;
    const float* src = feat + (size_t)s * SLICE;
    float* dst = d_integ4 + ((size_t)(cam * NCQ + (ch >> 2)) * SLICE) * 4 + (ch & 3);

    const int warp = threadIdx.x >> 5;
    const int lane = threadIdx.x & 31;

    // ---- row prefix scan: warp w handles rows w, w+8, ..., w+56 ----
    #pragma unroll
    for (int k = 0; k < 8; ++k) {              // independent rows -> ILP
        const int r = warp + k * 8;
        const float* row = src + (size_t)r * WF;
        float carry = 0.f;
        #pragma unroll
        for (int c = 0; c < 6; ++c) {          // 176 = 5*32 + 16
            const int x = c * 32 + lane;
            float v = (x < WF) ? row[x] : 0.f;
            #pragma unroll
            for (int o = 1; o < 32; o <<= 1) {
                const float n = __shfl_up_sync(0xffffffffu, v, o);
                if (lane >= o) v += n;
            }
            v += carry;
            if (x < WF) sh[r][x] = v;
            carry = __shfl_sync(0xffffffffu, v, 31);
        }
    }
    __syncthreads();

    // ---- column prefix + direct interleaved store ----
    if (threadIdx.x < WF) {
        const int x = threadIdx.x;
        float acc = 0.f;
        #pragma unroll 8
        for (int y = 0; y < HF; ++y) {
            acc += sh[y][x];
            dst[(size_t)(y * WF + x) * 4] = acc;
        }
    }
}

// ---------------- kernel 2: FUSED project + geometry ------------------------
__device__ __forceinline__ void map_axis(float c, int extent,
                                         int& i0, int& i1, float& w) {
    const float lim = (float)(extent - 1);
    const float v = fminf(fmaxf((c + 1.f) * 0.5f * lim, 0.f), lim);
    const float f = floorf(v);
    i0 = (int)f;
    w = v - f;
    i1 = min(i0 + 1, extent - 1);
}

__global__ void __launch_bounds__(128) oft_geometry(
        const float* __restrict__ ks,
        const float* __restrict__ imu2cs,
        const float* __restrict__ prs,
        const float* __restrict__ ptr_,
        const float* __restrict__ und,
        const float* __restrict__ grid) {
    __shared__ float2 sp[2][2][XD];    // [ny][z][x]
    const int blk = blockIdx.x;        // (cam*NH + nh)*DD + d
    const int d   = blk % DD;
    const int nh  = (blk / DD) % NH;
    const int cam = blk / (DD * NH);

    const float* K = ks + cam * 9;
    const float* M = imu2cs + cam * 12;
    float cal[12];
    #pragma unroll
    for (int i = 0; i < 3; ++i)
        #pragma unroll
        for (int j = 0; j < 4; ++j)
            cal[i * 4 + j] = K[i * 3 + 0] * M[0 * 4 + j]
                           + K[i * 3 + 1] * M[1 * 4 + j]
                           + K[i * 3 + 2] * M[2 * 4 + j];
    const float fx = K[0], fy = K[4], cx = K[2], cy = K[5];
    const float* D = und + cam * 7;
    const float* PR = prs + cam * 9;
    const float* PT = ptr_ + cam * 3;

    for (int i = threadIdx.x; i < 2 * 2 * XD; i += blockDim.x) {
        const int x = i % XD;
        const int b = (i / XD) & 1;    // z offset
        const int a = i / (XD * 2);    // ny offset
        const float* g = grid + (size_t)((d + b) * XD + x) * 3;
        const float X = g[0];
        const float Y = g[1] + (2.0f - (float)(nh + a));  // ys = -arange(0,4)+2
        const float Z = g[2];

        float hx = cal[0] * X + cal[1] * Y + cal[2]  * Z + cal[3];
        float hy = cal[4] * X + cal[5] * Y + cal[6]  * Z + cal[7];
        float hz = cal[8] * X + cal[9] * Y + cal[10] * Z + cal[11];
        const bool pos = hz > 0.f;
        if (!pos) { hx = 0.f; hy = 0.f; }        // flag zeroes x,y behind cam
        const float px = hx / hz;
        const float py = hy / hz;

        const float xn = (px - cx) / fx;
        const float yn = (py - cy) / fy;
        float xd, yd;
        if (D[6] == 1.0f) {                      // fisheye
            const float r  = sqrtf(xn * xn + yn * yn);
            const float th = atanf(r);
            const float t2 = th * th, t4 = t2 * t2, t6 = t4 * t2, t8 = t4 * t4;
            const float rad = th * (1.f + D[0] * t2 + D[1] * t4 + D[2] * t6 + D[5] * t8) / r;
            xd = xn * rad * fx + cx;
            yd = yn * rad * fy + cy;
        } else {                                 // pinhole + tangential
            const float k1 = D[0], k2 = D[1], k3 = D[2], p1 = D[3], p2 = D[4];
            const float r2 = xn * xn + yn * yn;
            const float poly = 1.f + k1 * r2 + k2 * r2 * r2 + k3 * r2 * r2 * r2;
            const float xdd = xn * poly + (2.f * p1 * xn * yn + p2 * (r2 + 2.f * xn * xn));
            const float ydd = yn * poly + (p1 * (r2 + 2.f * yn * yn) + 2.f * p2 * xn * yn);
            xd = xdd * fx + cx;
            yd = ydd * fy + cy;
        }
        const float fl = pos ? 1.f : 0.f;
        xd *= fl; yd *= fl;

        const float qx = PR[0] * xd + PR[1] * yd + PT[0];
        const float qy = PR[3] * xd + PR[4] * yd + PT[1];
        sp[a][b][x] = make_float2(fminf(fmaxf(2.f * qx - 1.f, -1.f), 1.f),
                                  fminf(fmaxf(2.f * qy - 1.f, -1.f), 1.f));
    }
    __syncthreads();

    const int wd = threadIdx.x;
    float left = FLT_MAX, right = -FLT_MAX, top = FLT_MAX, bot = -FLT_MAX;
    #pragma unroll
    for (int a = 0; a < 2; ++a)
        #pragma unroll
        for (int b = 0; b < 2; ++b)
            #pragma unroll
            for (int c = 0; c < 2; ++c) {
                const float2 v = sp[a][b][wd + c];
                left  = fminf(left,  v.x);  right = fmaxf(right, v.x);
                top   = fminf(top,   v.y);  bot   = fmaxf(bot,   v.y);
            }

    const float area = (right - left) * (bot - top) * ((float)HF * (float)WF * 0.25f) + EPS_F;
    const float sc = (area > EPS_F) ? (1.f / area) : 0.f;

    int xl0, xl1, xr0, xr1, yt0, yt1, yb0, yb1;
    float wxl, wxr, wyt, wyb;
    map_axis(left,  WF, xl0, xl1, wxl);
    map_axis(right, WF, xr0, xr1, wxr);
    map_axis(top,   HF, yt0, yt1, wyt);
    map_axis(bot,   HF, yb0, yb1, wyb);

    const int idx = (cam * NH + nh) * P + d * WDIM + wd;
    // value = sum_j wb_j * sum_i wa_i * I[yo_j + xi_i]  (tl+br-tr-bl separable)
    g_xi[idx] = make_int4(xl0, xl1, xr0, xr1);
    g_wa[idx] = make_float4(1.f - wxl, wxl, -(1.f - wxr), -wxr);
    g_yo[idx] = make_int4(yt0 * WF, yt1 * WF, yb0 * WF, yb1 * WF);
    g_wb[idx] = make_float4(1.f - wyt, wyt, -(1.f - wyb), -wyb);
    g_sc[idx] = sc;
}

// ---------------- float4 helpers -------------------------------------------
__device__ __forceinline__ float4 f4_scale(float s, float4 a) {
    return make_float4(s * a.x, s * a.y, s * a.z, s * a.w);
}
__device__ __forceinline__ float4 f4_fma(float s, float4 a, float4 acc) {
    return make_float4(fmaf(s, a.x, acc.x), fmaf(s, a.y, acc.y),
                       fmaf(s, a.z, acc.z), fmaf(s, a.w, acc.w));
}

// ---------------- kernel 3: gather + max over cameras (dominant) ------------
// R8 configuration verbatim — best measured: 68.8us, occ 56.9, L1 78.2%.
__global__ void __launch_bounds__(256, 5) oft_sample(float* __restrict__ out) {
    const int t = blockIdx.x * blockDim.x + threadIdx.x;
    const int p  = t & (P - 1);
    const int nh = (t >> 14) % NH;
    const int cq = t / (P * NH);          // channel quad 0..15

    float4 m = make_float4(-INFINITY, -INFINITY, -INFINITY, -INFINITY);

    #pragma unroll
    for (int cam = 0; cam < NCAM; ++cam) {
        const int rec = (cam * NH + nh) * P + p;
        const float sc = __ldg(&g_sc[rec]);
        if (sc != 0.f) {
            const int4   xi = __ldg(&g_xi[rec]);
            const int4   yo = __ldg(&g_yo[rec]);
            const float4 wa = __ldg(&g_wa[rec]);
            const float4 wb = __ldg(&g_wb[rec]);
            const float4* base = reinterpret_cast<const float4*>(d_integ4)
                               + (size_t)(cam * NCQ + cq) * SLICE;

            float4 acc;
            {
                const float4* r = base + yo.x;
                float4 s = f4_scale(wa.x, __ldg(r + xi.x));
                s = f4_fma(wa.y, __ldg(r + xi.y), s);
                s = f4_fma(wa.z, __ldg(r + xi.z), s);
                s = f4_fma(wa.w, __ldg(r + xi.w), s);
                acc = f4_scale(wb.x, s);
            }
            {
                const float4* r = base + yo.y;
                float4 s = f4_scale(wa.x, __ldg(r + xi.x));
                s = f4_fma(wa.y, __ldg(r + xi.y), s);
                s = f4_fma(wa.z, __ldg(r + xi.z), s);
                s = f4_fma(wa.w, __ldg(r + xi.w), s);
                acc = f4_fma(wb.y, s, acc);
            }
            {
                const float4* r = base + yo.z;
                float4 s = f4_scale(wa.x, __ldg(r + xi.x));
                s = f4_fma(wa.y, __ldg(r + xi.y), s);
                s = f4_fma(wa.z, __ldg(r + xi.z), s);
                s = f4_fma(wa.w, __ldg(r + xi.w), s);
                acc = f4_fma(wb.z, s, acc);
            }
            {
                const float4* r = base + yo.w;
                float4 s = f4_scale(wa.x, __ldg(r + xi.x));
                s = f4_fma(wa.y, __ldg(r + xi.y), s);
                s = f4_fma(wa.z, __ldg(r + xi.z), s);
                s = f4_fma(wa.w, __ldg(r + xi.w), s);
                acc = f4_fma(wb.w, s, acc);
            }
            m.x = fmaxf(m.x, acc.x * sc);
            m.y = fmaxf(m.y, acc.y * sc);
            m.z = fmaxf(m.z, acc.z * sc);
            m.w = fmaxf(m.w, acc.w * sc);
        } else {
            m.x = fmaxf(m.x, 0.f);
            m.y = fmaxf(m.y, 0.f);
            m.z = fmaxf(m.z, 0.f);
            m.w = fmaxf(m.w, 0.f);
        }
    }

    float* o = out + (size_t)(cq * 4 * NH + nh) * P + p;
    o[0]                  = m.x;
    o[(size_t)NH * P]     = m.y;
    o[(size_t)2 * NH * P] = m.z;
    o[(size_t)3 * NH * P] = m.w;
}

// ---------------- launch --------------------------------------------------
extern "C" void kernel_launch(void* const* d_in, const int* in_sizes, int n_in,
                              void* d_out, int out_size) {
    const float* features  = (const float*)d_in[0];
    const float* ks        = (const float*)d_in[1];
    const float* imu2cs    = (const float*)d_in[2];
    const float* post_rots = (const float*)d_in[3];
    const float* post_tran = (const float*)d_in[4];
    const float* undists   = (const float*)d_in[5];
    const float* grid      = (const float*)d_in[6];
    float* out = (float*)d_out;

    oft_integral<<<NCAM * CCH, 256>>>(features);

    oft_geometry<<<NCAM * NH * DD, 128>>>(ks, imu2cs, post_rots, post_tran,
                                          undists, grid);

    const int nsamp = NCQ * NH * P;            // 786432 threads
    oft_sample<<<(nsamp + 255) / 256, 256>>>(out);
}